// round 1
// baseline (speedup 1.0000x reference)
#include <cuda_runtime.h>
#include <cuda_bf16.h>
#include <stdint.h>

// Problem constants (fixed by the reference):
//   text: (S=200, B=2048) integer tokens in [0, V=50000)
//   w_weight: (1, V) float32 ; w_bias: (1,) float32
//   out[b] = sum_s w_weight[text[s,b]] + bias   -> 2048 floats
#define S_TOK 200
#define B_PHR 2048
#define S_PER_PART 25   // 200 / 8 partitions

// dtype-detection flag: 1 if text is int64, 0 if int32.
__device__ int g_is64;

// Values are < 50000 and nonnegative; if the buffer is int64 (little-endian),
// every odd 32-bit word is zero. Check 31 odd words -> false-positive
// probability on genuine int32 data ~ (1/50000)^31 ~ 0.
__global__ void MNB_detect_kernel(const unsigned int* __restrict__ text32) {
    int all_zero = 1;
#pragma unroll
    for (int i = 1; i < 64; i += 2) {
        if (text32[i] != 0u) { all_zero = 0; }
    }
    g_is64 = all_zero;
}

__global__ __launch_bounds__(256) void MNB_455266533601_kernel(
    const void* __restrict__ text_raw,
    const float* __restrict__ w_weight,
    const float* __restrict__ w_bias,
    float* __restrict__ out)
{
    const int lane = threadIdx.x & 31;   // phrase within block
    const int sp   = threadIdx.x >> 5;   // s-partition 0..7
    const int b    = (blockIdx.x << 5) + lane;
    const int s0   = sp * S_PER_PART;

    float acc = 0.0f;

    if (g_is64) {
        const long long* __restrict__ text = (const long long*)text_raw;
        int idx[S_PER_PART];
        // Batch the (coalesced) index loads first for memory-level parallelism,
        // then issue all gathers (L2-resident 200KB table).
#pragma unroll
        for (int i = 0; i < S_PER_PART; i++) {
            idx[i] = (int)text[(size_t)(s0 + i) * B_PHR + b];
        }
#pragma unroll
        for (int i = 0; i < S_PER_PART; i++) {
            acc += __ldg(&w_weight[idx[i]]);
        }
    } else {
        const int* __restrict__ text = (const int*)text_raw;
        int idx[S_PER_PART];
#pragma unroll
        for (int i = 0; i < S_PER_PART; i++) {
            idx[i] = text[(size_t)(s0 + i) * B_PHR + b];
        }
#pragma unroll
        for (int i = 0; i < S_PER_PART; i++) {
            acc += __ldg(&w_weight[idx[i]]);
        }
    }

    __shared__ float red[8][32];
    red[sp][lane] = acc;
    __syncthreads();

    if (sp == 0) {
        float sum = red[0][lane] + red[1][lane] + red[2][lane] + red[3][lane]
                  + red[4][lane] + red[5][lane] + red[6][lane] + red[7][lane];
        out[b] = sum + __ldg(w_bias);
    }
}

extern "C" void kernel_launch(void* const* d_in, const int* in_sizes, int n_in,
                              void* d_out, int out_size) {
    const void*  text   = d_in[0];                    // (S, B) int32 or int64
    const float* weight = (const float*)d_in[1];      // (1, V) float32
    const float* bias   = (const float*)d_in[2];      // (1,) float32
    float*       out    = (float*)d_out;              // (B, 1) float32

    MNB_detect_kernel<<<1, 1>>>((const unsigned int*)text);
    MNB_455266533601_kernel<<<B_PHR / 32, 256>>>(text, weight, bias, out);
}

// round 2
// speedup vs baseline: 3.3833x; 3.3833x over previous
#include <cuda_runtime.h>
#include <cuda_bf16.h>
#include <stdint.h>

// out[b] = sum_{s=0}^{199} w_weight[text[s,b]] + bias ;  text (200, 2048) row-major
#define S_TOK 200
#define B_PHR 2048
#define PHR_PER_BLK 8          // phrases per block
#define NBLK (B_PHR / PHR_PER_BLK)   // 256 blocks
#define NGRP 32                // s-groups per block (one per 8-thread slice)

__global__ __launch_bounds__(256) void MNB_455266533601_kernel(
    const void* __restrict__ text_raw,
    const float* __restrict__ w_weight,
    const float* __restrict__ w_bias,
    float* __restrict__ out)
{
    const int tid   = threadIdx.x;
    const int laneb = tid & 7;          // phrase within block (0..7)
    const int g     = tid >> 3;         // s-group (0..31)
    const int b     = blockIdx.x * PHR_PER_BLK + laneb;

    // ---- dtype detection, fused (no separate launch) ----
    // Tokens are in [0, 50000). If the buffer is int64 (little-endian), every
    // odd 32-bit word is a zero high-half. Each warp checks 32 distinct odd
    // words and votes; false-positive on genuine int32 data ~ (1/50000)^32.
    const unsigned int* __restrict__ t32 = (const unsigned int*)text_raw;
    unsigned int probe = t32[2 * (tid & 31) + 1];
    const bool is64 = __all_sync(0xffffffffu, probe == 0u);

    // s-groups 0..7 take 7 tokens, 8..31 take 6  (8*7 + 24*6 = 200)
    const int cnt = (g < 8) ? 7 : 6;
    const int s0  = (g < 8) ? g * 7 : 56 + (g - 8) * 6;

    // Batch coalesced index loads first (MLP), then the random gathers.
    int idx[7];
    if (is64) {
        const long long* __restrict__ t = (const long long*)text_raw;
#pragma unroll
        for (int i = 0; i < 7; i++)
            if (i < cnt) idx[i] = (int)t[(size_t)(s0 + i) * B_PHR + b];
    } else {
        const int* __restrict__ t = (const int*)text_raw;
#pragma unroll
        for (int i = 0; i < 7; i++)
            if (i < cnt) idx[i] = t[(s0 + i) * B_PHR + b];
    }

    float acc = 0.0f;
#pragma unroll
    for (int i = 0; i < 7; i++)
        if (i < cnt) acc += __ldg(&w_weight[idx[i]]);

    // ---- reduce 32 s-group partials per phrase ----
    __shared__ float red[NGRP][PHR_PER_BLK];   // [32][8] floats, conflict-free
    red[g][laneb] = acc;
    __syncthreads();

    if (tid < PHR_PER_BLK) {
        float sum = 0.0f;
#pragma unroll
        for (int j = 0; j < NGRP; j++) sum += red[j][tid];
        out[blockIdx.x * PHR_PER_BLK + tid] = sum + __ldg(w_bias);
    }
}

extern "C" void kernel_launch(void* const* d_in, const int* in_sizes, int n_in,
                              void* d_out, int out_size) {
    const void*  text   = d_in[0];                 // (200, 2048) int32 or int64
    const float* weight = (const float*)d_in[1];   // (1, 50000) float32
    const float* bias   = (const float*)d_in[2];   // (1,) float32
    float*       out    = (float*)d_out;           // (2048, 1) float32

    MNB_455266533601_kernel<<<NBLK, 256>>>(text, weight, bias, out);
}